// round 17
// baseline (speedup 1.0000x reference)
#include <cuda_runtime.h>
#include <cuda_bf16.h>
#include <math.h>
#include <stdint.h>

// ---------------- problem constants (fixed by the reference) ----------------
#define BB 2
#define LL 2048
#define HH 768
#define EE 1536
#define NNS 16           // state dim N
#define RRK 4            // dt rank R
#define CC 3
#define NLAYER 8
#define TT (BB*LL)       // 4096 rows
#define NCH 16           // scan chunks per sequence
#define TCH (LL/NCH)     // 128 steps per chunk

// ---------------- scratch (device globals: no runtime allocation) ----------
__device__ float g_hs  [TT*HH];
__device__ float g_proj[TT*2*EE];
__device__ float g_u   [TT*EE];
__device__ float g_dbc [TT*36];
__device__ float g_dt  [TT*EE];
__device__ float g_cP   [BB*NCH*NNS*EE];
__device__ float g_cH   [BB*NCH*NNS*EE];
__device__ float g_hinit[BB*NCH*NNS*EE];
__device__ float g_t3  [CC*TT*HH];       // fractal 3rd-step outputs per branch

// bf16 hi/lo split buffers (activations)
__device__ __nv_bfloat16 g_Ah [TT*EE];   // layer activations (max K = 1536)
__device__ __nv_bfloat16 g_Al [TT*EE];
__device__ __nv_bfloat16 g_Ah2[TT*HH];   // hs splits (fractal input, z-shared)
__device__ __nv_bfloat16 g_Al2[TT*HH];
__device__ __nv_bfloat16 g_F1h[CC*TT*HH], g_F1l[CC*TT*HH];  // fractal t1 per branch
__device__ __nv_bfloat16 g_F2h[CC*TT*HH], g_F2l[CC*TT*HH];  // fractal t2 per branch

// precomputed weight splits, transposed to [N,K] per layer (all layers upfront)
__device__ __nv_bfloat16 g_Wih[(size_t)NLAYER*HH*2*EE];
__device__ __nv_bfloat16 g_Wil[(size_t)NLAYER*HH*2*EE];
__device__ __nv_bfloat16 g_Woh[(size_t)NLAYER*EE*HH];
__device__ __nv_bfloat16 g_Wol[(size_t)NLAYER*EE*HH];
__device__ __nv_bfloat16 g_Wfh[(size_t)NLAYER*CC*HH*HH];
__device__ __nv_bfloat16 g_Wfl[(size_t)NLAYER*CC*HH*HH];

// ---------------- helpers ----------------
__device__ __forceinline__ float silu_f(float v)    { return v / (1.0f + expf(-v)); }
__device__ __forceinline__ float sigmoid_f(float v) { return 1.0f / (1.0f + expf(-v)); }
__device__ __forceinline__ float softplus_f(float v){ return (v > 20.0f) ? v : log1pf(expf(v)); }

__device__ __forceinline__ void mma16816(float* d, const uint32_t* a, const uint32_t* b)
{
    asm volatile(
        "mma.sync.aligned.m16n8k16.row.col.f32.bf16.bf16.f32 "
        "{%0,%1,%2,%3}, {%4,%5,%6,%7}, {%8,%9}, {%0,%1,%2,%3};"
        : "+f"(d[0]), "+f"(d[1]), "+f"(d[2]), "+f"(d[3])
        : "r"(a[0]), "r"(a[1]), "r"(a[2]), "r"(a[3]), "r"(b[0]), "r"(b[1]));
}
__device__ __forceinline__ void ldsm4(uint32_t* r, const __nv_bfloat16* p)
{
    uint32_t sa = (uint32_t)__cvta_generic_to_shared(p);
    asm volatile("ldmatrix.sync.aligned.m8n8.x4.shared.b16 {%0,%1,%2,%3}, [%4];"
                 : "=r"(r[0]), "=r"(r[1]), "=r"(r[2]), "=r"(r[3]) : "r"(sa));
}
__device__ __forceinline__ void cpa16(__nv_bfloat16* s, const __nv_bfloat16* g)
{
    uint32_t sa = (uint32_t)__cvta_generic_to_shared(s);
    asm volatile("cp.async.cg.shared.global [%0], [%1], 16;" :: "r"(sa), "l"(g));
}
__device__ __forceinline__ void split_store(__nv_bfloat16* Oh, __nv_bfloat16* Ol,
                                            size_t idx, float v0, float v1)
{
    __nv_bfloat16 h0 = __float2bfloat16(v0), h1 = __float2bfloat16(v1);
    __nv_bfloat162 hv; hv.x = h0; hv.y = h1;
    *(__nv_bfloat162*)(Oh + idx) = hv;
    __nv_bfloat162 lv;
    lv.x = __float2bfloat16(v0 - __bfloat162float(h0));
    lv.y = __float2bfloat16(v1 - __bfloat162float(h1));
    *(__nv_bfloat162*)(Ol + idx) = lv;
}

// ---------------- embedding ----------------
__global__ void embed_kernel(const int* __restrict__ ids,
                             const float* __restrict__ tok,
                             const float* __restrict__ pos,
                             float* __restrict__ hs)
{
    int g = blockIdx.x * blockDim.x + threadIdx.x;   // TT*HH
    if (g >= TT*HH) return;
    int h   = g % HH;
    int row = g / HH;
    int t   = row % LL;
    hs[g] = tok[(size_t)ids[row]*HH + h] + pos[(size_t)t*HH + h];
}

// ---------------- layernorm; optional float out and/or bf16 hi/lo split ----
__global__ __launch_bounds__(256) void ln_kernel(const float* __restrict__ in,
                                                 const float* __restrict__ w,
                                                 const float* __restrict__ b,
                                                 float* __restrict__ out,
                                                 __nv_bfloat16* __restrict__ oh,
                                                 __nv_bfloat16* __restrict__ ol)
{
    __shared__ float red[256];
    int row = blockIdx.x, tid = threadIdx.x;
    const float* x = in + (size_t)row*HH;
    float v0 = x[tid], v1 = x[tid+256], v2 = x[tid+512];
    red[tid] = v0 + v1 + v2;
    __syncthreads();
    #pragma unroll
    for (int s = 128; s > 0; s >>= 1) { if (tid < s) red[tid] += red[tid+s]; __syncthreads(); }
    float mean = red[0] * (1.0f/768.0f);
    __syncthreads();
    float d0 = v0-mean, d1 = v1-mean, d2 = v2-mean;
    red[tid] = d0*d0 + d1*d1 + d2*d2;
    __syncthreads();
    #pragma unroll
    for (int s = 128; s > 0; s >>= 1) { if (tid < s) red[tid] += red[tid+s]; __syncthreads(); }
    float inv = rsqrtf(red[0] * (1.0f/768.0f) + 1e-5f);
    size_t base = (size_t)row*HH;
    #pragma unroll
    for (int q = 0; q < 3; q++) {
        float dd = (q == 0) ? d0 : (q == 1) ? d1 : d2;
        int h = tid + q*256;
        float vv = dd*inv*w[h] + b[h];
        if (out) out[base + h] = vv;
        if (oh) {
            __nv_bfloat16 hb = __float2bfloat16(vv);
            oh[base + h] = hb;
            ol[base + h] = __float2bfloat16(vv - __bfloat162float(hb));
        }
    }
}

// ---------------- weight transpose + split: W[K,N] -> Wt[N,K] hi/lo --------
__global__ __launch_bounds__(256) void convW_kernel(const float* __restrict__ W,
                                                    __nv_bfloat16* __restrict__ Wth,
                                                    __nv_bfloat16* __restrict__ Wtl,
                                                    int Kd, int Nd)
{
    __shared__ float tile[32][33];
    size_t zo = (size_t)blockIdx.z * Kd * Nd;
    W += zo; Wth += zo; Wtl += zo;
    int kb = blockIdx.y*32, nb = blockIdx.x*32;
    int tx = threadIdx.x & 31, ty = threadIdx.x >> 5;   // 32x8
    #pragma unroll
    for (int r = 0; r < 32; r += 8)
        tile[ty+r][tx] = W[(size_t)(kb+ty+r)*Nd + nb+tx];
    __syncthreads();
    #pragma unroll
    for (int r = 0; r < 32; r += 8) {
        int n = nb + ty + r, k = kb + tx;
        float v = tile[tx][ty+r];
        __nv_bfloat16 h = __float2bfloat16(v);
        Wth[(size_t)n*Kd + k] = h;
        Wtl[(size_t)n*Kd + k] = __float2bfloat16(v - __bfloat162float(h));
    }
}

// ---------------- tensor-core split-bf16 GEMM: 3-stage cp.async ------------
// C = act(A*W + bias) [+res] [accum] ; optional bf16 hi/lo split output.
// D = Ah*Bh^T + Ah*Bl^T + Al*Bh^T, fp32 accumulate; product-major MMA order.
// Block 128(M)x64(N), 4 warps (2m x 2n), warp tile 64x32 (16 independent
// accumulators between same-acc reuse; 128B smem per HMMA), KC=32, 3 stages.
// blockIdx.z batches independent GEMMs via az/wz/bz/oz element strides.
#define KC  32
#define AST 40                          // smem row stride (bf16): conflict-free
#define TILE_A (128*AST)
#define TILE_B (64*AST)
#define STAGE_E (2*TILE_A + 2*TILE_B)   // 15360 elems
#define MM_SMEM (3*STAGE_E*2)           // 92160 bytes

__global__ __launch_bounds__(128, 2) void mma_gemm(
    const __nv_bfloat16* __restrict__ Ah, const __nv_bfloat16* __restrict__ Al,
    const __nv_bfloat16* __restrict__ Bh, const __nv_bfloat16* __restrict__ Bl,
    const float* __restrict__ bias, const float* __restrict__ Rres,
    float* __restrict__ Cout,
    __nv_bfloat16* __restrict__ Oh, __nv_bfloat16* __restrict__ Ol,
    int Kd, int Nd, int act, int accum,
    long az, long wz, int bz, long oz)
{
    extern __shared__ __align__(16) __nv_bfloat16 sm[];
    const int tid = threadIdx.x, wid = tid >> 5, lane = tid & 31;
    const int bm = blockIdx.y*128, bn = blockIdx.x*64;
    const int wm = (wid & 1)*64, wn = (wid >> 1)*32;
    const int r = lane >> 2, c = lane & 3;
    const int z = blockIdx.z;

    Ah += (size_t)az*z; Al += (size_t)az*z;
    Bh += (size_t)wz*z; Bl += (size_t)wz*z;
    bias += (size_t)bz*z;

    float acc[4][4][4];
    #pragma unroll
    for (int mt = 0; mt < 4; mt++)
        #pragma unroll
        for (int nt = 0; nt < 4; nt++)
            #pragma unroll
            for (int j = 0; j < 4; j++) acc[mt][nt][j] = 0.0f;

    auto issue_fill = [&](int stage, int kc) {
        const size_t koff = (size_t)kc * KC;
        __nv_bfloat16* S = sm + stage*STAGE_E;
        #pragma unroll
        for (int i = 0; i < 4; i++) {                 // A: 512 uint4 / tile
            int q = tid + i*128;
            int row = q >> 2, col = (q & 3)*8;
            int so = row*AST + col;
            size_t ga = (size_t)(bm + row)*Kd + koff + col;
            cpa16(S + so,          Ah + ga);
            cpa16(S + TILE_A + so, Al + ga);
        }
        #pragma unroll
        for (int i = 0; i < 2; i++) {                 // B: 256 uint4 / tile
            int q = tid + i*128;
            int row = q >> 2, col = (q & 3)*8;
            int so = row*AST + col;
            size_t gb = (size_t)(bn + row)*Kd + koff + col;
            cpa16(S + 2*TILE_A + so,          Bh + gb);
            cpa16(S + 2*TILE_A + TILE_B + so, Bl + gb);
        }
        asm volatile("cp.async.commit_group;" ::: "memory");
    };

    const int nkc = Kd / KC;
    issue_fill(0, 0);
    issue_fill(1, 1);
    int stage = 0;
    for (int kc = 0; kc < nkc; kc++) {
        if (kc + 1 < nkc) { asm volatile("cp.async.wait_group 1;" ::: "memory"); }
        else              { asm volatile("cp.async.wait_group 0;" ::: "memory"); }
        __syncthreads();
        if (kc + 2 < nkc) {
            int ns = stage + 2; if (ns >= 3) ns -= 3;
            issue_fill(ns, kc + 2);
        }
        const __nv_bfloat16* S   = sm + stage*STAGE_E;
        const __nv_bfloat16* Ash = S;
        const __nv_bfloat16* Asl = S + TILE_A;
        const __nv_bfloat16* Bsh = S + 2*TILE_A;
        const __nv_bfloat16* Bsl = S + 2*TILE_A + TILE_B;

        #pragma unroll
        for (int kk = 0; kk < KC; kk += 16) {
            uint32_t afh[4][4], afl[4][4], bh[2][4], bl[2][4];
            #pragma unroll
            for (int mt = 0; mt < 4; mt++) {
                int ae = (wm + mt*16 + (lane & 15))*AST + kk + ((lane >> 4)*8);
                ldsm4(afh[mt], Ash + ae);
                ldsm4(afl[mt], Asl + ae);
            }
            #pragma unroll
            for (int nt2 = 0; nt2 < 2; nt2++) {
                int be = (wn + nt2*16 + ((lane >> 4)*8) + (lane & 7))*AST
                         + kk + (((lane >> 3) & 1)*8);
                ldsm4(bh[nt2], Bsh + be);
                ldsm4(bl[nt2], Bsl + be);
            }
            // product-major: 16 independent accumulators between reuses
            #pragma unroll
            for (int mt = 0; mt < 4; mt++)
                #pragma unroll
                for (int nt2 = 0; nt2 < 2; nt2++)
                    #pragma unroll
                    for (int h = 0; h < 2; h++)
                        mma16816(acc[mt][nt2*2 + h], afh[mt], bh[nt2] + 2*h);
            #pragma unroll
            for (int mt = 0; mt < 4; mt++)
                #pragma unroll
                for (int nt2 = 0; nt2 < 2; nt2++)
                    #pragma unroll
                    for (int h = 0; h < 2; h++)
                        mma16816(acc[mt][nt2*2 + h], afh[mt], bl[nt2] + 2*h);
            #pragma unroll
            for (int mt = 0; mt < 4; mt++)
                #pragma unroll
                for (int nt2 = 0; nt2 < 2; nt2++)
                    #pragma unroll
                    for (int h = 0; h < 2; h++)
                        mma16816(acc[mt][nt2*2 + h], afl[mt], bh[nt2] + 2*h);
        }
        stage++; if (stage >= 3) stage = 0;
    }

    // epilogue: fragment (rows r, r+8; cols 2c, 2c+1)
    #pragma unroll
    for (int nt = 0; nt < 4; nt++) {
        int n = bn + wn + nt*8 + 2*c;
        float2 bv = *(const float2*)(bias + n);
        #pragma unroll
        for (int mt = 0; mt < 4; mt++) {
            #pragma unroll
            for (int half = 0; half < 2; half++) {
                int m = bm + wm + mt*16 + r + half*8;
                float v0 = acc[mt][nt][half*2+0] + bv.x;
                float v1 = acc[mt][nt][half*2+1] + bv.y;
                if (act) { v0 = silu_f(v0); v1 = silu_f(v1); }
                size_t idx = (size_t)m * Nd + n + (size_t)oz*z;
                if (Rres) { float2 rv = *(const float2*)(Rres + idx); v0 += rv.x; v1 += rv.y; }
                if (Cout) {
                    if (accum) {
                        float2 ov = *(const float2*)(Cout + idx);
                        v0 += ov.x; v1 += ov.y;
                    }
                    float2 w2; w2.x = v0; w2.y = v1;
                    *(float2*)(Cout + idx) = w2;
                }
                if (Oh) split_store(Oh, Ol, idx, v0, v1);
            }
        }
    }
}

// ---------------- causal depthwise conv (K=4) + SiLU, reads xm from proj ----
__global__ void conv_silu_kernel(const float* __restrict__ proj,
                                 const float* __restrict__ cw,
                                 const float* __restrict__ cb,
                                 float* __restrict__ u)
{
    int g = blockIdx.x * blockDim.x + threadIdx.x;   // TT*EE
    if (g >= TT*EE) return;
    int e   = g % EE;
    int row = g / EE;
    int t   = row % LL;
    int b   = row / LL;
    float acc = cb[e];
    #pragma unroll
    for (int j = 0; j < 4; j++) {
        int tt = t - 3 + j;
        if (tt >= 0)
            acc = fmaf(proj[(size_t)(b*LL + tt)*(2*EE) + e], cw[e*4 + j], acc);
    }
    u[g] = silu_f(acc);
}

// ---------------- dbc = u @ xproj_w  (4096 x 1536 x 36 skinny GEMM) --------
__global__ __launch_bounds__(288) void dbc_kernel(const float* __restrict__ u,
                                                  const float* __restrict__ w,
                                                  float* __restrict__ dbc)
{
    __shared__ float su[EE];
    __shared__ float part[8][36];
    int row = blockIdx.x;
    for (int i = threadIdx.x; i < EE; i += 288) su[i] = u[(size_t)row*EE + i];
    __syncthreads();
    int j = threadIdx.x % 36, s = threadIdx.x / 36;   // 36 cols x 8 k-slices
    float acc = 0.0f;
    int k0 = s * (EE/8);
    for (int k = k0; k < k0 + EE/8; k++)
        acc = fmaf(su[k], w[k*36 + j], acc);
    part[s][j] = acc;
    __syncthreads();
    if (threadIdx.x < 36) {
        float t = 0.0f;
        #pragma unroll
        for (int ss = 0; ss < 8; ss++) t += part[ss][threadIdx.x];
        dbc[row*36 + threadIdx.x] = t;
    }
}

// ---------------- dt = softplus(dbc[:, :4] @ dt_w + dt_b) ------------------
__global__ void dt_kernel(const float* __restrict__ dbc,
                          const float* __restrict__ dtw,
                          const float* __restrict__ dtb,
                          float* __restrict__ dt)
{
    int g = blockIdx.x * blockDim.x + threadIdx.x;   // TT*EE
    if (g >= TT*EE) return;
    int e = g % EE, row = g / EE;
    float v = dtb[e];
    #pragma unroll
    for (int r = 0; r < 4; r++)
        v = fmaf(dbc[row*36 + r], dtw[r*EE + e], v);
    dt[g] = softplus_f(v);
}

// ---------------- scan pass A (n-folded): per-chunk (prod dA, h'|h0=0) -----
__global__ __launch_bounds__(256) void scan_chunk_kernel(
    const float* __restrict__ dtp, const float* __restrict__ up,
    const float* __restrict__ dbc, const float* __restrict__ A_log,
    float* __restrict__ cP, float* __restrict__ cH)
{
    int g = blockIdx.x * blockDim.x + threadIdx.x;   // BB*NCH*EE
    if (g >= BB*NCH*EE) return;
    int e = g % EE;
    int c = (g / EE) % NCH;
    int b =  g / (EE*NCH);
    float Aen[NNS], p[NNS], h[NNS];
    #pragma unroll
    for (int n = 0; n < NNS; n++) {
        Aen[n] = -expf(A_log[e*NNS + n]);
        p[n] = 1.0f; h[n] = 0.0f;
    }
    int rbase = b*LL + c*TCH;
    for (int t = 0; t < TCH; t++) {
        int row   = rbase + t;
        float dtv = dtp[(size_t)row*EE + e];
        float uv  = up [(size_t)row*EE + e];
        float du  = dtv * uv;
        const float* bvp = dbc + row*36 + 4;
        #pragma unroll
        for (int n = 0; n < NNS; n++) {
            float dA = expf(dtv * Aen[n]);
            p[n] *= dA;
            h[n] = fmaf(h[n], dA, du * bvp[n]);
        }
    }
    size_t base = ((size_t)((b*NCH + c)*NNS))*EE + e;
    #pragma unroll
    for (int n = 0; n < NNS; n++) {
        cP[base + (size_t)n*EE] = p[n];
        cH[base + (size_t)n*EE] = h[n];
    }
}

// ---------------- scan pass B: sequential carry across 16 chunks -----------
__global__ void scan_carry_kernel(const float* __restrict__ cP,
                                  const float* __restrict__ cH,
                                  float* __restrict__ hinit)
{
    int g = blockIdx.x * blockDim.x + threadIdx.x;   // BB*NNS*EE
    if (g >= BB*NNS*EE) return;
    int e = g % EE;
    int n = (g / EE) % NNS;
    int b =  g / (EE*NNS);
    float h = 0.0f;
    for (int c = 0; c < NCH; c++) {
        size_t idx = ((size_t)((b*NCH + c)*NNS + n))*EE + e;
        hinit[idx] = h;
        h = fmaf(cP[idx], h, cH[idx]);
    }
}

// ---------------- scan pass C (n-folded): rescan + gate -> y bf16 hi/lo ----
__global__ __launch_bounds__(256) void scan_y_kernel(
    const float* __restrict__ dtp, const float* __restrict__ up,
    const float* __restrict__ dbc, const float* __restrict__ hinit,
    const float* __restrict__ A_log, const float* __restrict__ Dv,
    const float* __restrict__ proj,
    __nv_bfloat16* __restrict__ yh, __nv_bfloat16* __restrict__ yl)
{
    int g = blockIdx.x * blockDim.x + threadIdx.x;   // BB*NCH*EE
    if (g >= BB*NCH*EE) return;
    int e = g % EE;
    int c = (g / EE) % NCH;
    int b =  g / (EE*NCH);
    float Aen[NNS], h[NNS];
    size_t hbase = ((size_t)((b*NCH + c)*NNS))*EE + e;
    #pragma unroll
    for (int n = 0; n < NNS; n++) {
        Aen[n] = -expf(A_log[e*NNS + n]);
        h[n] = hinit[hbase + (size_t)n*EE];
    }
    float Dval = Dv[e];
    int rbase = b*LL + c*TCH;
    for (int t = 0; t < TCH; t++) {
        int row   = rbase + t;
        float dtv = dtp[(size_t)row*EE + e];
        float uv  = up [(size_t)row*EE + e];
        float du  = dtv * uv;
        const float* bvp = dbc + row*36 + 4;
        const float* cvp = dbc + row*36 + 20;
        float acc = 0.0f;
        #pragma unroll
        for (int n = 0; n < NNS; n++) {
            h[n] = fmaf(h[n], expf(dtv * Aen[n]), du * bvp[n]);
            acc = fmaf(h[n], cvp[n], acc);
        }
        float gate = proj[(size_t)row*(2*EE) + EE + e];
        float yv = (acc + uv*Dval) * sigmoid_f(gate);
        size_t yi = (size_t)row*EE + e;
        __nv_bfloat16 hb = __float2bfloat16(yv);
        yh[yi] = hb;
        yl[yi] = __float2bfloat16(yv - __bfloat162float(hb));
    }
}

// ---------------- fractal accumulation: hs += (0.5/C)*sum_z t3[z] ----------
__global__ void frac_add3_kernel(float* __restrict__ hs, const float* __restrict__ t3, int n)
{
    int g = blockIdx.x * blockDim.x + threadIdx.x;
    if (g < n)
        hs[g] = fmaf(t3[g] + t3[n + g] + t3[2*n + g], 0.5f/3.0f, hs[g]);
}

// ---------------- host orchestration ----------------
extern "C" void kernel_launch(void* const* d_in, const int* in_sizes, int n_in,
                              void* d_out, int out_size)
{
    const int*   input_ids = (const int*)  d_in[0];
    const float* tok_emb   = (const float*)d_in[1];
    const float* pos_emb   = (const float*)d_in[2];
    const float* ln_w      = (const float*)d_in[3];
    const float* ln_b      = (const float*)d_in[4];
    const float* in_w      = (const float*)d_in[5];
    const float* in_b      = (const float*)d_in[6];
    const float* conv_w    = (const float*)d_in[7];
    const float* conv_b    = (const float*)d_in[8];
    const float* xproj_w   = (const float*)d_in[9];
    const float* dt_w      = (const float*)d_in[10];
    const float* dt_b      = (const float*)d_in[11];
    const float* A_log     = (const float*)d_in[12];
    const float* Dvec      = (const float*)d_in[13];
    const float* out_w     = (const float*)d_in[14];
    const float* out_b     = (const float*)d_in[15];
    const float* frac_w    = (const float*)d_in[16];
    const float* frac_b    = (const float*)d_in[17];
    const float* fln_w     = (const float*)d_in[18];
    const float* fln_b     = (const float*)d_in[19];
    float* outp = (float*)d_out;

    cudaFuncSetAttribute(mma_gemm, cudaFuncAttributeMaxDynamicSharedMemorySize,
                         MM_SMEM);

    float *hs, *proj, *u, *dbc, *dt, *cP, *cH, *hinit, *t3;
    cudaGetSymbolAddress((void**)&hs,    g_hs);
    cudaGetSymbolAddress((void**)&proj,  g_proj);
    cudaGetSymbolAddress((void**)&u,     g_u);
    cudaGetSymbolAddress((void**)&dbc,   g_dbc);
    cudaGetSymbolAddress((void**)&dt,    g_dt);
    cudaGetSymbolAddress((void**)&cP,    g_cP);
    cudaGetSymbolAddress((void**)&cH,    g_cH);
    cudaGetSymbolAddress((void**)&hinit, g_hinit);
    cudaGetSymbolAddress((void**)&t3,    g_t3);

    __nv_bfloat16 *Ah, *Al, *Ah2, *Al2, *F1h, *F1l, *F2h, *F2l;
    __nv_bfloat16 *Wih, *Wil, *Woh, *Wol, *Wfh, *Wfl;
    cudaGetSymbolAddress((void**)&Ah,  g_Ah);
    cudaGetSymbolAddress((void**)&Al,  g_Al);
    cudaGetSymbolAddress((void**)&Ah2, g_Ah2);
    cudaGetSymbolAddress((void**)&Al2, g_Al2);
    cudaGetSymbolAddress((void**)&F1h, g_F1h);
    cudaGetSymbolAddress((void**)&F1l, g_F1l);
    cudaGetSymbolAddress((void**)&F2h, g_F2h);
    cudaGetSymbolAddress((void**)&F2l, g_F2l);
    cudaGetSymbolAddress((void**)&Wih, g_Wih);
    cudaGetSymbolAddress((void**)&Wil, g_Wil);
    cudaGetSymbolAddress((void**)&Woh, g_Woh);
    cudaGetSymbolAddress((void**)&Wol, g_Wol);
    cudaGetSymbolAddress((void**)&Wfh, g_Wfh);
    cudaGetSymbolAddress((void**)&Wfl, g_Wfl);

    const int EW  = TT*HH;
    const int EWE = TT*EE;
    const int SCAN_NF = BB*NCH*EE;     // n-folded scan thread count
    const long ZF = (long)TT*HH;       // fractal per-branch stride

    // one-time weight split/transpose for ALL layers (batched over z)
    convW_kernel<<<dim3(2*EE/32, HH/32, NLAYER), 256>>>(in_w,  Wih, Wil, HH, 2*EE);
    convW_kernel<<<dim3(HH/32, EE/32, NLAYER), 256>>>(out_w, Woh, Wol, EE, HH);
    convW_kernel<<<dim3(HH/32, HH/32, NLAYER*CC), 256>>>(frac_w, Wfh, Wfl, HH, HH);

    embed_kernel<<<(EW + 255)/256, 256>>>(input_ids, tok_emb, pos_emb, hs);

    for (int l = 0; l < NLAYER; l++) {
        // x = LN(hs) -> bf16 hi/lo only (feeds GEMM directly)
        ln_kernel<<<TT, 256>>>(hs, ln_w + l*HH, ln_b + l*HH, nullptr, Ah, Al);
        // proj = x @ in_w + in_b  (4096 x 768 x 3072)
        mma_gemm<<<dim3(2*EE/64, TT/128), 128, MM_SMEM>>>(
            Ah, Al, Wih + (size_t)l*HH*2*EE, Wil + (size_t)l*HH*2*EE,
            in_b + l*2*EE, nullptr, proj, nullptr, nullptr,
            HH, 2*EE, 0, 0, 0, 0, 0, 0);
        // u = silu(causal_dwconv(proj[:, :E]))
        conv_silu_kernel<<<(EWE + 255)/256, 256>>>(proj, conv_w + l*EE*4, conv_b + l*EE, u);
        // dbc = u @ xproj_w
        dbc_kernel<<<TT, 288>>>(u, xproj_w + (size_t)l*EE*36, dbc);
        // dt = softplus(dbc[:, :4] @ dt_w + dt_b)
        dt_kernel<<<(EWE + 255)/256, 256>>>(dbc, dt_w + l*RRK*EE, dt_b + l*EE, dt);
        // chunked selective scan (n-folded passes A and C)
        scan_chunk_kernel<<<(SCAN_NF + 255)/256, 256>>>(
            dt, u, dbc, A_log + (size_t)l*EE*NNS, cP, cH);
        scan_carry_kernel<<<(BB*NNS*EE + 255)/256, 256>>>(cP, cH, hinit);
        scan_y_kernel<<<(SCAN_NF + 255)/256, 256>>>(dt, u, dbc, hinit,
            A_log + (size_t)l*EE*NNS, Dvec + l*EE, proj, Ah, Al);
        // hs = y @ out_w + out_b + hs; also emit hs splits for fractal input
        mma_gemm<<<dim3(HH/64, TT/128), 128, MM_SMEM>>>(
            Ah, Al, Woh + (size_t)l*EE*HH, Wol + (size_t)l*EE*HH,
            out_b + l*HH, hs, hs, Ah2, Al2,
            EE, HH, 0, 0, 0, 0, 0, 0);
        // fractal refinement: 3 independent branches batched over blockIdx.z
        const __nv_bfloat16* Wfh_l = Wfh + (size_t)l*CC*HH*HH;
        const __nv_bfloat16* Wfl_l = Wfl + (size_t)l*CC*HH*HH;
        const float* fb_l = frac_b + (size_t)l*CC*HH;
        mma_gemm<<<dim3(HH/64, TT/128, CC), 128, MM_SMEM>>>(
            Ah2, Al2, Wfh_l, Wfl_l, fb_l, nullptr, nullptr, F1h, F1l,
            HH, HH, 1, 0, 0, (long)HH*HH, HH, ZF);
        mma_gemm<<<dim3(HH/64, TT/128, CC), 128, MM_SMEM>>>(
            F1h, F1l, Wfh_l, Wfl_l, fb_l, nullptr, nullptr, F2h, F2l,
            HH, HH, 1, 0, ZF, (long)HH*HH, HH, ZF);
        mma_gemm<<<dim3(HH/64, TT/128, CC), 128, MM_SMEM>>>(
            F2h, F2l, Wfh_l, Wfl_l, fb_l, nullptr, t3, nullptr, nullptr,
            HH, HH, 1, 0, ZF, (long)HH*HH, HH, ZF);
        // hs += (0.5/C) * sum_z t3_z
        frac_add3_kernel<<<(EW + 255)/256, 256>>>(hs, t3, EW);
    }

    // final layernorm -> output (float32)
    ln_kernel<<<TT, 256>>>(hs, fln_w, fln_b, outp, nullptr, nullptr);
    (void)in_sizes; (void)n_in; (void)out_size;
}